// round 16
// baseline (speedup 1.0000x reference)
#include <cuda_runtime.h>
#include <cuda_bf16.h>
#include <cstdint>
#include <math.h>

#define B_    8192
#define T_    30
#define D_    256
#define H_    8
#define L_    6
#define SD_   8
#define FF_   1024
#define CF_   256
#define BT_   (B_*T_)
#define KP_   320   // 296 padded to multiple of 64
#define NAD_  6144  // 12 * 512 batched adaLN output width
#define WSC   64.f  // fp8 weight pre-scale
#define WSCI  (1.f/64.f)

// ============================ ptx helpers ============================
#define SWZ(x) ((x) ^ (((x) >> 3) & 0x70))

static __device__ __forceinline__ uint32_t s2u(const void* p){
    uint32_t a;
    asm("{ .reg .u64 t; cvta.to.shared.u64 t, %1; cvt.u32.u64 %0, t; }" : "=r"(a) : "l"(p));
    return a;
}
static __device__ __forceinline__ void cpa16(uint32_t s, const void* g){
    asm volatile("cp.async.cg.shared.global [%0], [%1], 16;" :: "r"(s), "l"(g));
}
#define CP_COMMIT() asm volatile("cp.async.commit_group;" ::: "memory")
#define CP_WAIT1()  asm volatile("cp.async.wait_group 1;" ::: "memory")
#define CP_WAIT0()  asm volatile("cp.async.wait_group 0;" ::: "memory")

static __device__ __forceinline__ void ldm4(uint32_t a, uint32_t* r){
    asm volatile("ldmatrix.sync.aligned.m8n8.x4.shared.b16 {%0,%1,%2,%3}, [%4];"
        : "=r"(r[0]), "=r"(r[1]), "=r"(r[2]), "=r"(r[3]) : "r"(a));
}
static __device__ __forceinline__ void mma16816(float* d,
    uint32_t a0, uint32_t a1, uint32_t a2, uint32_t a3, uint32_t b0, uint32_t b1){
    asm volatile(
        "mma.sync.aligned.m16n8k16.row.col.f32.bf16.bf16.f32 "
        "{%0,%1,%2,%3}, {%4,%5,%6,%7}, {%8,%9}, {%0,%1,%2,%3};"
        : "+f"(d[0]), "+f"(d[1]), "+f"(d[2]), "+f"(d[3])
        : "r"(a0), "r"(a1), "r"(a2), "r"(a3), "r"(b0), "r"(b1));
}
static __device__ __forceinline__ void mma8(float* d,
    uint32_t a0, uint32_t a1, uint32_t a2, uint32_t a3, uint32_t b0, uint32_t b1){
    asm volatile(
        "mma.sync.aligned.m16n8k32.row.col.f32.e4m3.e4m3.f32 "
        "{%0,%1,%2,%3}, {%4,%5,%6,%7}, {%8,%9}, {%0,%1,%2,%3};"
        : "+f"(d[0]), "+f"(d[1]), "+f"(d[2]), "+f"(d[3])
        : "r"(a0), "r"(a1), "r"(a2), "r"(a3), "r"(b0), "r"(b1));
}
// pack two f32 -> e4m3x2 (lo in low byte, hi in high byte)
static __device__ __forceinline__ uint16_t pk8(float lo, float hi){
    uint16_t r;
    asm("cvt.rn.satfinite.e4m3x2.f32 %0, %1, %2;" : "=h"(r) : "f"(hi), "f"(lo));
    return r;
}
// unpack e4m3x2 -> two f32
static __device__ __forceinline__ float2 up8(uint16_t pr){
    uint32_t h2;
    asm("cvt.rn.f16x2.e4m3x2 %0, %1;" : "=r"(h2) : "h"(pr));
    __half2 hh = *(__half2*)&h2;
    return __half22float2(hh);
}

// ============================ scratch ============================
__device__ float g_adb[NAD_];
__device__ float g_u  [B_*SD_];
__device__ float g_part[1024];
__device__ __align__(256) __nv_bfloat16 g_ssb[(size_t)B_*NAD_];  // adaLN out (bf16)
__device__ __align__(256) __nv_bfloat16 g_xb [(size_t)BT_*D_];   // residual (bf16)
__device__ __align__(256) uint8_t g_hq8 [(size_t)BT_*768];       // qkv out (fp8)
__device__ __align__(256) uint8_t g_x2b8[(size_t)BT_*D_];        // modln / attn out (fp8)
__device__ __align__(256) uint8_t g_hb8 [(size_t)BT_*FF_];       // silu(ff1) out (fp8)
__device__ __align__(256) __nv_bfloat16 g_cb [B_*CF_];
__device__ __align__(256) __nv_bfloat16 g_canvb[B_*384];
__device__ __align__(256) __nv_bfloat16 g_f1b[B_*512];
__device__ __align__(256) __nv_bfloat16 g_f2b[B_*512];
__device__ __align__(256) __nv_bfloat16 g_xinb[B_*KP_];
__device__ __align__(256) __nv_bfloat16 g_wce1[512*384];
__device__ __align__(256) __nv_bfloat16 g_wce2[256*512];
__device__ __align__(256) __nv_bfloat16 g_wad [NAD_*256];
__device__ __align__(256) uint8_t g_w8inp[(size_t)L_*768*256];   // fp8 weights (x64)
__device__ __align__(256) uint8_t g_w8out[(size_t)L_*256*256];
__device__ __align__(256) uint8_t g_w8ff1[(size_t)L_*1024*256];
__device__ __align__(256) uint8_t g_w8ff2[(size_t)L_*256*1024];
__device__ __align__(256) __nv_bfloat16 g_wfm1[512*KP_];
__device__ __align__(256) __nv_bfloat16 g_wfm2[512*512];

#define GSMEM (3*32768 + 1024)

// ============================ bf16 GEMM (R10, unchanged) ============================
static __device__ __forceinline__ void load_stage(
    uint32_t ab, int s, const __nv_bfloat16* A, const __nv_bfloat16* W,
    int K, int bm, int bn, int k0, int tid)
{
    uint32_t as_ = ab + s*32768;
    uint32_t bs_ = as_ + 16384;
    const __nv_bfloat16* Ap = A + (size_t)bm*K + k0;
    const __nv_bfloat16* Wp = W + (size_t)bn*K + k0;
#pragma unroll
    for (int t = 0; t < 4; t++) {
        int idx = tid + t*256;
        int row = idx >> 3, c16 = idx & 7;
        uint32_t off = (uint32_t)(row*128 + c16*16);
        cpa16(as_ + SWZ(off), Ap + (size_t)row*K + c16*8);
    }
#pragma unroll
    for (int t = 0; t < 4; t++) {
        int idx = tid + t*256;
        int row = idx >> 3, c16 = idx & 7;
        uint32_t off = (uint32_t)(row*128 + c16*16);
        cpa16(bs_ + SWZ(off), Wp + (size_t)row*K + c16*8);
    }
}

template<int EPI, int OUTBF>
__global__ __launch_bounds__(256, 2)
void gemm_tc(const __nv_bfloat16* __restrict__ A, const __nv_bfloat16* __restrict__ W,
             const float* __restrict__ bias, void* __restrict__ Cout,
             const void* __restrict__ res, int M, int N, int K)
{
    extern __shared__ char smem[];
    const int tid = threadIdx.x;
    uint32_t sraw = s2u(smem);
    uint32_t ab = (sraw + 1023) & ~1023u;
    char* smemc = smem + (ab - sraw);
    const int bm = blockIdx.y * 128;
    const int bn = blockIdx.x * 128;
    const int lane = tid & 31, wid = tid >> 5;
    const int wm = (wid & 3) * 32;
    const int wn = (wid >> 2) * 64;

    float acc[2][8][4];
#pragma unroll
    for (int a = 0; a < 2; a++)
#pragma unroll
        for (int b = 0; b < 8; b++)
#pragma unroll
            for (int c = 0; c < 4; c++) acc[a][b][c] = 0.f;

    const int nch = K >> 6;
    load_stage(ab, 0, A, W, K, bm, bn, 0,  tid); CP_COMMIT();
    load_stage(ab, 1, A, W, K, bm, bn, 64, tid); CP_COMMIT();

    const int r16 = lane & 15;
    const uint32_t cg = (uint32_t)((lane >> 4) << 4);

    int s = 0;
    for (int i = 0; i < nch; i++) {
        CP_WAIT1();
        __syncthreads();
        if (i + 2 < nch) {
            int s2 = s + 2; if (s2 >= 3) s2 -= 3;
            load_stage(ab, s2, A, W, K, bm, bn, (i+2)*64, tid);
        }
        CP_COMMIT();

        const uint32_t as_ = ab + s*32768;
        const uint32_t bs_ = as_ + 16384;
#pragma unroll
        for (int k16 = 0; k16 < 4; k16++) {
            uint32_t af[2][4], bfr[4][4];
#pragma unroll
            for (int mt = 0; mt < 2; mt++) {
                uint32_t off = (uint32_t)((wm + mt*16 + r16)*128 + k16*32) + cg;
                ldm4(as_ + SWZ(off), af[mt]);
            }
#pragma unroll
            for (int nt2 = 0; nt2 < 4; nt2++) {
                uint32_t off = (uint32_t)((wn + nt2*16 + r16)*128 + k16*32) + cg;
                ldm4(bs_ + SWZ(off), bfr[nt2]);
            }
#pragma unroll
            for (int mt = 0; mt < 2; mt++)
#pragma unroll
                for (int nt2 = 0; nt2 < 4; nt2++) {
                    mma16816(acc[mt][nt2*2],   af[mt][0], af[mt][1], af[mt][2], af[mt][3],
                             bfr[nt2][0], bfr[nt2][2]);
                    mma16816(acc[mt][nt2*2+1], af[mt][0], af[mt][1], af[mt][2], af[mt][3],
                             bfr[nt2][1], bfr[nt2][3]);
                }
        }
        if (++s >= 3) s = 0;
    }
    CP_WAIT0();
    __syncthreads();

    float* smemT = (float*)smemc;
    {
        const int r4 = lane >> 2;
        const int c2 = (lane & 3) << 1;
#pragma unroll
        for (int mt = 0; mt < 2; mt++)
#pragma unroll
            for (int nt = 0; nt < 8; nt++) {
                int row = wm + mt*16 + r4;
                int col = wn + nt*8 + c2;
                *(float2*)&smemT[row*132 + col]     = make_float2(acc[mt][nt][0], acc[mt][nt][1]);
                *(float2*)&smemT[(row+8)*132 + col] = make_float2(acc[mt][nt][2], acc[mt][nt][3]);
            }
    }
    __syncthreads();
#pragma unroll
    for (int it = 0; it < 16; it++) {
        int idx = tid + it*256;
        int row = idx >> 5;
        int c4  = (idx & 31) << 2;
        float4 v = *(float4*)&smemT[row*132 + c4];
        float4 bb = *(const float4*)&bias[bn + c4];
        v.x += bb.x; v.y += bb.y; v.z += bb.z; v.w += bb.w;
        if (EPI == 1) {
            v.x *= 1.f/(1.f + __expf(-v.x));
            v.y *= 1.f/(1.f + __expf(-v.y));
            v.z *= 1.f/(1.f + __expf(-v.z));
            v.w *= 1.f/(1.f + __expf(-v.w));
        }
        size_t g = (size_t)(bm + row)*N + bn + c4;
        if (OUTBF) {
            __nv_bfloat162 p0 = __floats2bfloat162_rn(v.x, v.y);
            __nv_bfloat162 p1 = __floats2bfloat162_rn(v.z, v.w);
            uint2 u2;
            u2.x = *(uint32_t*)&p0; u2.y = *(uint32_t*)&p1;
            *(uint2*)((__nv_bfloat16*)Cout + g) = u2;
        } else {
            *(float4*)((float*)Cout + g) = v;
        }
    }
}

// ============================ fp8 GEMM (R15, unchanged) ============================
static __device__ __forceinline__ void load_stage8(
    uint32_t ab, int s, const uint8_t* A, const uint8_t* W,
    int K, int bm, int bn, int k0, int tid)
{
    uint32_t as_ = ab + s*32768;
    uint32_t bs_ = as_ + 16384;
    const uint8_t* Ap = A + (size_t)bm*K + k0;
    const uint8_t* Wp = W + (size_t)bn*K + k0;
#pragma unroll
    for (int t = 0; t < 4; t++) {
        int idx = tid + t*256;
        int row = idx >> 3, c16 = idx & 7;
        uint32_t off = (uint32_t)(row*128 + c16*16);
        cpa16(as_ + SWZ(off), Ap + (size_t)row*K + c16*16);
    }
#pragma unroll
    for (int t = 0; t < 4; t++) {
        int idx = tid + t*256;
        int row = idx >> 3, c16 = idx & 7;
        uint32_t off = (uint32_t)(row*128 + c16*16);
        cpa16(bs_ + SWZ(off), Wp + (size_t)row*K + c16*16);
    }
}

template<int EPI, int OUT8>
__global__ __launch_bounds__(256, 2)
void gemm8(const uint8_t* __restrict__ A, const uint8_t* __restrict__ W,
           const float* __restrict__ bias, void* __restrict__ Cout,
           const void* __restrict__ res, int M, int N, int K)
{
    extern __shared__ char smem[];
    const int tid = threadIdx.x;
    uint32_t sraw = s2u(smem);
    uint32_t ab = (sraw + 1023) & ~1023u;
    char* smemc = smem + (ab - sraw);
    const int bm = blockIdx.y * 128;
    const int bn = blockIdx.x * 128;
    const int lane = tid & 31, wid = tid >> 5;
    const int wm = (wid & 3) * 32;
    const int wn = (wid >> 2) * 64;

    float acc[2][8][4];
#pragma unroll
    for (int a = 0; a < 2; a++)
#pragma unroll
        for (int b = 0; b < 8; b++)
#pragma unroll
            for (int c = 0; c < 4; c++) acc[a][b][c] = 0.f;

    const int nch = K >> 7;
    load_stage8(ab, 0, A, W, K, bm, bn, 0,   tid); CP_COMMIT();
    if (nch > 1) load_stage8(ab, 1, A, W, K, bm, bn, 128, tid);
    CP_COMMIT();

    const int r16 = lane & 15;
    const uint32_t cg = (uint32_t)((lane >> 4) << 4);

    int s = 0;
    for (int i = 0; i < nch; i++) {
        CP_WAIT1();
        __syncthreads();
        if (i + 2 < nch) {
            int s2 = s + 2; if (s2 >= 3) s2 -= 3;
            load_stage8(ab, s2, A, W, K, bm, bn, (i+2)*128, tid);
        }
        CP_COMMIT();

        const uint32_t as_ = ab + s*32768;
        const uint32_t bs_ = as_ + 16384;
#pragma unroll
        for (int k32 = 0; k32 < 4; k32++) {
            uint32_t af[2][4], bfr[4][4];
#pragma unroll
            for (int mt = 0; mt < 2; mt++) {
                uint32_t off = (uint32_t)((wm + mt*16 + r16)*128 + k32*32) + cg;
                ldm4(as_ + SWZ(off), af[mt]);
            }
#pragma unroll
            for (int nt2 = 0; nt2 < 4; nt2++) {
                uint32_t off = (uint32_t)((wn + nt2*16 + r16)*128 + k32*32) + cg;
                ldm4(bs_ + SWZ(off), bfr[nt2]);
            }
#pragma unroll
            for (int mt = 0; mt < 2; mt++)
#pragma unroll
                for (int nt2 = 0; nt2 < 4; nt2++) {
                    mma8(acc[mt][nt2*2],   af[mt][0], af[mt][1], af[mt][2], af[mt][3],
                         bfr[nt2][0], bfr[nt2][2]);
                    mma8(acc[mt][nt2*2+1], af[mt][0], af[mt][1], af[mt][2], af[mt][3],
                         bfr[nt2][1], bfr[nt2][3]);
                }
        }
        if (++s >= 3) s = 0;
    }
    CP_WAIT0();
    __syncthreads();

    float* smemT = (float*)smemc;
    {
        const int r4 = lane >> 2;
        const int c2 = (lane & 3) << 1;
#pragma unroll
        for (int mt = 0; mt < 2; mt++)
#pragma unroll
            for (int nt = 0; nt < 8; nt++) {
                int row = wm + mt*16 + r4;
                int col = wn + nt*8 + c2;
                *(float2*)&smemT[row*132 + col]     = make_float2(acc[mt][nt][0], acc[mt][nt][1]);
                *(float2*)&smemT[(row+8)*132 + col] = make_float2(acc[mt][nt][2], acc[mt][nt][3]);
            }
    }
    __syncthreads();
#pragma unroll
    for (int it = 0; it < 16; it++) {
        int idx = tid + it*256;
        int row = idx >> 5;
        int c4  = (idx & 31) << 2;
        float4 v = *(float4*)&smemT[row*132 + c4];
        float4 bb = *(const float4*)&bias[bn + c4];
        v.x = v.x*WSCI + bb.x; v.y = v.y*WSCI + bb.y;
        v.z = v.z*WSCI + bb.z; v.w = v.w*WSCI + bb.w;
        if (EPI == 1) {
            v.x *= 1.f/(1.f + __expf(-v.x));
            v.y *= 1.f/(1.f + __expf(-v.y));
            v.z *= 1.f/(1.f + __expf(-v.z));
            v.w *= 1.f/(1.f + __expf(-v.w));
        }
        size_t g = (size_t)(bm + row)*N + bn + c4;
        if (EPI == 2) {
            uint2 rr = *(const uint2*)((const __nv_bfloat16*)res + g);
            __nv_bfloat162 r0 = *(__nv_bfloat162*)&rr.x;
            __nv_bfloat162 r1 = *(__nv_bfloat162*)&rr.y;
            v.x += __bfloat162float(r0.x); v.y += __bfloat162float(r0.y);
            v.z += __bfloat162float(r1.x); v.w += __bfloat162float(r1.y);
        }
        if (OUT8) {
            uint32_t ww = (uint32_t)pk8(v.x, v.y) | ((uint32_t)pk8(v.z, v.w) << 16);
            *(uint32_t*)((uint8_t*)Cout + g) = ww;
        } else {
            __nv_bfloat162 p0 = __floats2bfloat162_rn(v.x, v.y);
            __nv_bfloat162 p1 = __floats2bfloat162_rn(v.z, v.w);
            uint2 u2;
            u2.x = *(uint32_t*)&p0; u2.y = *(uint32_t*)&p1;
            *(uint2*)((__nv_bfloat16*)Cout + g) = u2;
        }
    }
}

// ============================ aux kernels ============================
__global__ void k_cvt(const float* __restrict__ s, __nv_bfloat16* __restrict__ d, int n)
{
    for (int i = blockIdx.x*blockDim.x + threadIdx.x; i < n; i += gridDim.x*blockDim.x)
        d[i] = __float2bfloat16(s[i]);
}

__global__ void k_cvt8(const float* __restrict__ s, uint8_t* __restrict__ d, int n)
{
    for (int i = (blockIdx.x*blockDim.x + threadIdx.x)*2; i < n; i += gridDim.x*blockDim.x*2)
        *(uint16_t*)(d + i) = pk8(s[i]*WSC, s[i+1]*WSC);
}

__global__ void k_cat(const float* __restrict__ b1, const float* __restrict__ b2,
                      float* __restrict__ d)
{
    int i = blockIdx.x*blockDim.x + threadIdx.x;
    d[i] = (i < 3072) ? b1[i] : b2[i - 3072];
}

__global__ __launch_bounds__(256)
void k_stroke(const float* __restrict__ strokes, const float* __restrict__ sp_w,
              const float* __restrict__ sp_b, const float* __restrict__ pos,
              __nv_bfloat16* __restrict__ x)
{
    int row = blockIdx.x;
    int t = row % T_;
    int d = threadIdx.x;
    float acc = sp_b[d] + pos[t*D_ + d];
#pragma unroll
    for (int j = 0; j < 8; j++)
        acc += strokes[(size_t)row*8 + j] * sp_w[d*8 + j];
    x[(size_t)row*D_ + d] = __float2bfloat16(acc);
}

static __device__ __forceinline__ void unp8b(uint4 u, float* v){
    __nv_bfloat162 p0 = *(__nv_bfloat162*)&u.x;
    __nv_bfloat162 p1 = *(__nv_bfloat162*)&u.y;
    __nv_bfloat162 p2 = *(__nv_bfloat162*)&u.z;
    __nv_bfloat162 p3 = *(__nv_bfloat162*)&u.w;
    v[0] = __bfloat162float(p0.x); v[1] = __bfloat162float(p0.y);
    v[2] = __bfloat162float(p1.x); v[3] = __bfloat162float(p1.y);
    v[4] = __bfloat162float(p2.x); v[5] = __bfloat162float(p2.y);
    v[6] = __bfloat162float(p3.x); v[7] = __bfloat162float(p3.y);
}

// warp-per-row adaLN modulate -> fp8 output; ss table in bf16
__global__ __launch_bounds__(256)
void k_modln(const __nv_bfloat16* __restrict__ x, const __nv_bfloat16* __restrict__ ss,
             uint8_t* __restrict__ x2, int off)
{
    int w = threadIdx.x >> 5, ln = threadIdx.x & 31;
    int row = blockIdx.x*8 + w;
    int b = row / T_;
    float v[8];
    unp8b(*(const uint4*)(x + (size_t)row*D_ + ln*8), v);
    float s = 0.f, q = 0.f;
#pragma unroll
    for (int j = 0; j < 8; j++) { s += v[j]; q += v[j]*v[j]; }
#pragma unroll
    for (int o = 16; o; o >>= 1) {
        s += __shfl_xor_sync(0xffffffffu, s, o);
        q += __shfl_xor_sync(0xffffffffu, q, o);
    }
    float mean = s * (1.f/256.f);
    float rstd = rsqrtf(q * (1.f/256.f) - mean*mean + 1e-5f);
    const __nv_bfloat16* ssb = ss + (size_t)b*NAD_ + off;
    float sc[8], sh[8];
    unp8b(*(const uint4*)&ssb[ln*8], sc);
    unp8b(*(const uint4*)&ssb[256 + ln*8], sh);
    float o8[8];
#pragma unroll
    for (int j = 0; j < 8; j++)
        o8[j] = (1.f + sc[j])*((v[j] - mean)*rstd) + sh[j];
    uint2 u2;
    u2.x = (uint32_t)pk8(o8[0], o8[1]) | ((uint32_t)pk8(o8[2], o8[3]) << 16);
    u2.y = (uint32_t)pk8(o8[4], o8[5]) | ((uint32_t)pk8(o8[6], o8[7]) << 16);
    *(uint2*)(x2 + (size_t)row*D_ + ln*8) = u2;
}

// ============================ attention (fp8 qkv input, fp8 output) ============================
#define QSTR 33
#define ASMEM (2*T_*256*4 + H_*T_*QSTR*4)   // 93120
__global__ __launch_bounds__(256)
void k_attn(const uint8_t* __restrict__ qkv, uint8_t* __restrict__ o)
{
    extern __shared__ float att[];
    float* ks = att;
    float* vs = att + T_*256;
    float* qs = att + 2*T_*256;
    int b = blockIdx.x;
    int tid = threadIdx.x;
    int h = tid >> 5, ln = tid & 31;

    // staging: 30*768 fp8 = 11520 pairs; 45 iters x 256 threads; coalesced u16 reads
#pragma unroll
    for (int it = 0; it < 45; it++) {
        int p = tid + it*256;
        int t = p / 384;
        int c2 = p - t*384;
        int d = c2*2;
        uint16_t pr = *(const uint16_t*)(qkv + ((size_t)(b*T_ + t))*768 + d);
        float2 f = up8(pr);
        if (d < 256) {
            int hh = d >> 5, dd = d & 31;
            float* qd = qs + hh*(T_*QSTR) + t*QSTR + dd;
            qd[0] = f.x; qd[1] = f.y;
        } else if (d < 512) {
            ks[t*256 + (d - 256)] = f.x;
            ks[t*256 + (d - 255)] = f.y;
        } else {
            vs[t*256 + (d - 512)] = f.x;
            vs[t*256 + (d - 511)] = f.y;
        }
    }
    __syncthreads();

    if (ln < T_) {
        const int q = ln;
        float qreg[32];
        const float* qh = qs + h*(T_*QSTR) + q*QSTR;
#pragma unroll
        for (int d = 0; d < 32; d++) qreg[d] = qh[d];
        const float* kh = ks + h*32;
        const float* vh = vs + h*32;
        const float scale = 0.17677669529663687f;

        float sc[T_];
#pragma unroll
        for (int k = 0; k < T_; k++) {
            float acc = 0.f;
#pragma unroll
            for (int d = 0; d < 32; d++) acc += qreg[d]*kh[k*256 + d];
            sc[k] = (k <= q) ? acc*scale : -1e30f;
        }
        float mx = -1e30f;
#pragma unroll
        for (int k = 0; k < T_; k++) mx = fmaxf(mx, sc[k]);
        float sm = 0.f;
#pragma unroll
        for (int k = 0; k < T_; k++) { sc[k] = __expf(sc[k] - mx); sm += sc[k]; }
        float inv = 1.f/sm;

        float o32[32];
#pragma unroll
        for (int d = 0; d < 32; d++) o32[d] = 0.f;
#pragma unroll
        for (int k = 0; k < T_; k++) {
            float a = sc[k]*inv;
            if (k <= q) {
#pragma unroll
                for (int d = 0; d < 32; d++) o32[d] += a*vh[k*256 + d];
            }
        }
        uint8_t* op = o + ((size_t)(b*T_ + q))*256 + h*32;
        uint32_t w8[8];
#pragma unroll
        for (int j = 0; j < 8; j++)
            w8[j] = (uint32_t)pk8(o32[j*4+0], o32[j*4+1]) | ((uint32_t)pk8(o32[j*4+2], o32[j*4+3]) << 16);
        *(uint4*)op = make_uint4(w8[0], w8[1], w8[2], w8[3]);
        *(uint4*)(op + 16) = make_uint4(w8[4], w8[5], w8[6], w8[7]);
    }
}

// fused head: final LN on last token + xin tail + u
__global__ __launch_bounds__(256)
void k_head(const __nv_bfloat16* __restrict__ x, const float* __restrict__ g,
            const float* __restrict__ be, const float* __restrict__ a_tar,
            const float* __restrict__ a_src, const float* __restrict__ t,
            __nv_bfloat16* __restrict__ xin, float* __restrict__ u)
{
    int w = threadIdx.x >> 5, ln = threadIdx.x & 31;
    int b = blockIdx.x*8 + w;
    float v[8];
    unp8b(*(const uint4*)(x + ((size_t)(b*T_ + T_ - 1))*D_ + ln*8), v);
    float s = 0.f, q = 0.f;
#pragma unroll
    for (int j = 0; j < 8; j++) { s += v[j]; q += v[j]*v[j]; }
#pragma unroll
    for (int o = 16; o; o >>= 1) {
        s += __shfl_xor_sync(0xffffffffu, s, o);
        q += __shfl_xor_sync(0xffffffffu, q, o);
    }
    float mean = s * (1.f/256.f);
    float rstd = rsqrtf(q * (1.f/256.f) - mean*mean + 1e-5f);
    size_t base = (size_t)b*KP_;
#pragma unroll
    for (int j = 0; j < 8; j++) {
        int d = ln*8 + j;
        xin[base + d] = __float2bfloat16(((v[j] - mean)*rstd)*g[d] + be[d]);
    }
    float tb = t[b];
    if (ln < 8) {
        float as = a_src[b*8+ln], at = a_tar[b*8+ln];
        xin[base + 256 + ln] = __float2bfloat16((1.f - tb)*as + tb*at);
        u[b*8+ln] = at - as;
    } else if (ln < 24) {
        int j = ln - 8;
        float freq = __expf(-9.210340371976184f * (float)j / 15.f);
        float arg = tb * freq;
        xin[base + 264 + j] = __float2bfloat16(sinf(arg));
        xin[base + 280 + j] = __float2bfloat16(cosf(arg));
    } else {
        int j0 = (ln - 24) * 3;
#pragma unroll
        for (int k = 0; k < 3; k++)
            xin[base + 296 + j0 + k] = __float2bfloat16(0.f);
    }
}

__global__ void k_padw(const float* __restrict__ w, __nv_bfloat16* __restrict__ wp)
{
    int n = blockIdx.x, k = threadIdx.x;
    wp[n*KP_ + k] = __float2bfloat16(k < 296 ? w[n*296 + k] : 0.f);
}

__global__ __launch_bounds__(256)
void k_fm3(const __nv_bfloat16* __restrict__ f2, const float* __restrict__ w3,
           const float* __restrict__ b3, const float* __restrict__ u,
           float* __restrict__ part)
{
    __shared__ float sp[8];
    int w = threadIdx.x >> 5, ln = threadIdx.x & 31;
    int b = blockIdx.x * 8 + w;
    float lsum = 0.f;
    const __nv_bfloat16* fr = f2 + (size_t)b*512;
#pragma unroll
    for (int n = 0; n < 8; n++) {
        const float* wr = w3 + n*512;
        float p = 0.f;
        for (int k = ln; k < 512; k += 32) p += __bfloat162float(fr[k])*wr[k];
#pragma unroll
        for (int o = 16; o; o >>= 1) p += __shfl_xor_sync(0xffffffffu, p, o);
        if (ln == 0) {
            float d = p + b3[n] - u[b*8+n];
            lsum += d*d;
        }
    }
    if (ln == 0) sp[w] = lsum;
    __syncthreads();
    if (threadIdx.x == 0) {
        float s = 0.f;
        for (int i = 0; i < 8; i++) s += sp[i];
        part[blockIdx.x] = s;
    }
}

__global__ void k_reduce(const float* __restrict__ part, float* __restrict__ out)
{
    __shared__ float sp[1024];
    int i = threadIdx.x;
    sp[i] = part[i];
    __syncthreads();
    for (int s = 512; s; s >>= 1) { if (i < s) sp[i] += sp[i+s]; __syncthreads(); }
    if (i == 0) out[0] = sp[0] * (1.f / (float)(B_*SD_));
}

// ============================ launch ============================
extern "C" void kernel_launch(void* const* d_in, const int* in_sizes, int n_in,
                              void* d_out, int out_size)
{
    const float* strokes  = (const float*)d_in[0];
    const float* canvas   = (const float*)d_in[1];
    const float* a_tar    = (const float*)d_in[2];
    const float* a_src    = (const float*)d_in[3];
    const float* t_in     = (const float*)d_in[4];
    const float* ce_w1    = (const float*)d_in[5];
    const float* ce_b1    = (const float*)d_in[6];
    const float* ce_w2    = (const float*)d_in[7];
    const float* ce_b2    = (const float*)d_in[8];
    const float* sp_w     = (const float*)d_in[9];
    const float* sp_b     = (const float*)d_in[10];
    const float* pos_emb  = (const float*)d_in[11];
    const float* adaln1_w = (const float*)d_in[12];
    const float* adaln1_b = (const float*)d_in[13];
    const float* inproj_w = (const float*)d_in[14];
    const float* inproj_b = (const float*)d_in[15];
    const float* outproj_w= (const float*)d_in[16];
    const float* outproj_b= (const float*)d_in[17];
    const float* adaln2_w = (const float*)d_in[18];
    const float* adaln2_b = (const float*)d_in[19];
    const float* ff1_w    = (const float*)d_in[20];
    const float* ff1_b    = (const float*)d_in[21];
    const float* ff2_w    = (const float*)d_in[22];
    const float* ff2_b    = (const float*)d_in[23];
    const float* on_g     = (const float*)d_in[24];
    const float* on_b     = (const float*)d_in[25];
    const float* fm_w1    = (const float*)d_in[26];
    const float* fm_b1    = (const float*)d_in[27];
    const float* fm_w2    = (const float*)d_in[28];
    const float* fm_b2    = (const float*)d_in[29];
    const float* fm_w3    = (const float*)d_in[30];
    const float* fm_b3    = (const float*)d_in[31];
    float* out = (float*)d_out;

    float *adb, *u, *part;
    __nv_bfloat16 *ssb, *xb, *cb, *canvb, *f1b, *f2b, *xinb;
    __nv_bfloat16 *wce1, *wce2, *wad, *wfm1, *wfm2;
    uint8_t *hq8, *x2b8, *hb8, *w8inp, *w8out, *w8ff1, *w8ff2;
    cudaGetSymbolAddress((void**)&adb,  g_adb);
    cudaGetSymbolAddress((void**)&u,    g_u);
    cudaGetSymbolAddress((void**)&part, g_part);
    cudaGetSymbolAddress((void**)&ssb,  g_ssb);
    cudaGetSymbolAddress((void**)&xb,   g_xb);
    cudaGetSymbolAddress((void**)&hq8,  g_hq8);
    cudaGetSymbolAddress((void**)&x2b8, g_x2b8);
    cudaGetSymbolAddress((void**)&hb8,  g_hb8);
    cudaGetSymbolAddress((void**)&cb,   g_cb);
    cudaGetSymbolAddress((void**)&canvb,g_canvb);
    cudaGetSymbolAddress((void**)&f1b,  g_f1b);
    cudaGetSymbolAddress((void**)&f2b,  g_f2b);
    cudaGetSymbolAddress((void**)&xinb, g_xinb);
    cudaGetSymbolAddress((void**)&wce1, g_wce1);
    cudaGetSymbolAddress((void**)&wce2, g_wce2);
    cudaGetSymbolAddress((void**)&wad,  g_wad);
    cudaGetSymbolAddress((void**)&w8inp,g_w8inp);
    cudaGetSymbolAddress((void**)&w8out,g_w8out);
    cudaGetSymbolAddress((void**)&w8ff1,g_w8ff1);
    cudaGetSymbolAddress((void**)&w8ff2,g_w8ff2);
    cudaGetSymbolAddress((void**)&wfm1, g_wfm1);
    cudaGetSymbolAddress((void**)&wfm2, g_wfm2);

    cudaFuncSetAttribute(gemm_tc<0,1>, cudaFuncAttributeMaxDynamicSharedMemorySize, GSMEM);
    cudaFuncSetAttribute(gemm_tc<1,1>, cudaFuncAttributeMaxDynamicSharedMemorySize, GSMEM);
    cudaFuncSetAttribute(gemm8<0,1>,   cudaFuncAttributeMaxDynamicSharedMemorySize, GSMEM);
    cudaFuncSetAttribute(gemm8<1,1>,   cudaFuncAttributeMaxDynamicSharedMemorySize, GSMEM);
    cudaFuncSetAttribute(gemm8<2,0>,   cudaFuncAttributeMaxDynamicSharedMemorySize, GSMEM);
    cudaFuncSetAttribute(k_attn,       cudaFuncAttributeMaxDynamicSharedMemorySize, ASMEM);

    // conversions
    k_cvt<<<1024, 256>>>(canvas,   canvb, B_*384);
    k_cvt<<<256,  256>>>(ce_w1,    wce1,  512*384);
    k_cvt<<<256,  256>>>(ce_w2,    wce2,  256*512);
    k_cvt<<<512,  256>>>(adaln1_w, wad,             L_*512*256);
    k_cvt<<<512,  256>>>(adaln2_w, wad + 3072*256,  L_*512*256);
    k_cat<<<24, 256>>>(adaln1_b, adaln2_b, adb);
    k_cvt8<<<512,  256>>>(inproj_w, w8inp, L_*768*256);
    k_cvt8<<<512,  256>>>(outproj_w,w8out, L_*256*256);
    k_cvt8<<<512,  256>>>(ff1_w,    w8ff1, L_*1024*256);
    k_cvt8<<<512,  256>>>(ff2_w,    w8ff2, L_*256*1024);
    k_cvt<<<256,  256>>>(fm_w2,    wfm2,  512*512);
    k_padw<<<512, KP_>>>(fm_w1, wfm1);

    // canvas encoder (bf16)
    gemm_tc<1,1><<<dim3(4,  64), 256, GSMEM>>>(canvb, wce1, ce_b1, f1b, nullptr, B_, 512, 384);
    gemm_tc<0,1><<<dim3(2,  64), 256, GSMEM>>>(f1b,   wce2, ce_b2, cb,  nullptr, B_, 256, 512);

    // batched adaLN (bf16 out)
    gemm_tc<0,1><<<dim3(48, 64), 256, GSMEM>>>(cb, wad, adb, ssb, nullptr, B_, NAD_, 256);

    // stroke projection
    k_stroke<<<BT_, 256>>>(strokes, sp_w, sp_b, pos_emb, xb);

    for (int l = 0; l < L_; l++) {
        k_modln<<<BT_/8, 256>>>(xb, ssb, x2b8, l*512);
        gemm8<0,1><<<dim3(6, 1920), 256, GSMEM>>>(x2b8, w8inp + (size_t)l*768*256,
                                                  inproj_b + l*768, hq8, nullptr, BT_, 768, 256);
        k_attn<<<B_, 256, ASMEM>>>(hq8, x2b8);
        gemm8<2,0><<<dim3(2, 1920), 256, GSMEM>>>(x2b8, w8out + (size_t)l*256*256,
                                                  outproj_b + l*256, xb, xb, BT_, 256, 256);
        k_modln<<<BT_/8, 256>>>(xb, ssb, x2b8, 3072 + l*512);
        gemm8<1,1><<<dim3(8, 1920), 256, GSMEM>>>(x2b8, w8ff1 + (size_t)l*1024*256,
                                                  ff1_b + l*1024, hb8, nullptr, BT_, 1024, 256);
        gemm8<2,0><<<dim3(2, 1920), 256, GSMEM>>>(hb8, w8ff2 + (size_t)l*256*1024,
                                                  ff2_b + l*256, xb, xb, BT_, 256, 1024);
    }

    // output head (bf16)
    k_head<<<B_/8, 256>>>(xb, on_g, on_b, a_tar, a_src, t_in, xinb, u);
    gemm_tc<1,1><<<dim3(4, 64), 256, GSMEM>>>(xinb, wfm1, fm_b1, f1b, nullptr, B_, 512, KP_);
    gemm_tc<1,1><<<dim3(4, 64), 256, GSMEM>>>(f1b,  wfm2, fm_b2, f2b, nullptr, B_, 512, 512);
    k_fm3<<<B_/8, 256>>>(f2b, fm_w3, fm_b3, u, part);
    k_reduce<<<1, 1024>>>(part, out);
}

// round 17
// speedup vs baseline: 1.1101x; 1.1101x over previous
#include <cuda_runtime.h>
#include <cuda_bf16.h>
#include <cstdint>
#include <math.h>

#define B_    8192
#define T_    30
#define D_    256
#define H_    8
#define L_    6
#define SD_   8
#define FF_   1024
#define CF_   256
#define BT_   (B_*T_)
#define KP_   320   // 296 padded to multiple of 64
#define NAD_  6144  // 12 * 512 batched adaLN output width

// ============================ ptx helpers ============================
#define SWZ(x) ((x) ^ (((x) >> 3) & 0x70))

static __device__ __forceinline__ uint32_t s2u(const void* p){
    uint32_t a;
    asm("{ .reg .u64 t; cvta.to.shared.u64 t, %1; cvt.u32.u64 %0, t; }" : "=r"(a) : "l"(p));
    return a;
}
static __device__ __forceinline__ void cpa16(uint32_t s, const void* g){
    asm volatile("cp.async.cg.shared.global [%0], [%1], 16;" :: "r"(s), "l"(g));
}
#define CP_COMMIT() asm volatile("cp.async.commit_group;" ::: "memory")
#define CP_WAIT1()  asm volatile("cp.async.wait_group 1;" ::: "memory")
#define CP_WAIT0()  asm volatile("cp.async.wait_group 0;" ::: "memory")

static __device__ __forceinline__ void ldm4(uint32_t a, uint32_t* r){
    asm volatile("ldmatrix.sync.aligned.m8n8.x4.shared.b16 {%0,%1,%2,%3}, [%4];"
        : "=r"(r[0]), "=r"(r[1]), "=r"(r[2]), "=r"(r[3]) : "r"(a));
}
static __device__ __forceinline__ void mma16816(float* d,
    uint32_t a0, uint32_t a1, uint32_t a2, uint32_t a3, uint32_t b0, uint32_t b1){
    asm volatile(
        "mma.sync.aligned.m16n8k16.row.col.f32.bf16.bf16.f32 "
        "{%0,%1,%2,%3}, {%4,%5,%6,%7}, {%8,%9}, {%0,%1,%2,%3};"
        : "+f"(d[0]), "+f"(d[1]), "+f"(d[2]), "+f"(d[3])
        : "r"(a0), "r"(a1), "r"(a2), "r"(a3), "r"(b0), "r"(b1));
}

// ============================ scratch ============================
__device__ float g_ss [(size_t)B_*NAD_];   // batched adaLN outputs
__device__ float g_adb[NAD_];              // concatenated adaLN biases
__device__ float g_u  [B_*SD_];
__device__ float g_part[1024];
__device__ __align__(256) __nv_bfloat16 g_xb [(size_t)BT_*D_];   // residual stream (bf16)
__device__ __align__(256) __nv_bfloat16 g_x2b[(size_t)BT_*D_];
__device__ __align__(256) __nv_bfloat16 g_hb [(size_t)BT_*FF_];
__device__ __align__(256) __nv_bfloat16 g_cb [B_*CF_];
__device__ __align__(256) __nv_bfloat16 g_canvb[B_*384];
__device__ __align__(256) __nv_bfloat16 g_f1b[B_*512];
__device__ __align__(256) __nv_bfloat16 g_f2b[B_*512];
__device__ __align__(256) __nv_bfloat16 g_xinb[B_*KP_];
__device__ __align__(256) __nv_bfloat16 g_wce1[512*384];
__device__ __align__(256) __nv_bfloat16 g_wce2[256*512];
__device__ __align__(256) __nv_bfloat16 g_wad [NAD_*256];
__device__ __align__(256) __nv_bfloat16 g_winp[L_*768*256];
__device__ __align__(256) __nv_bfloat16 g_wout[L_*256*256];
__device__ __align__(256) __nv_bfloat16 g_wff1[(size_t)L_*1024*256];
__device__ __align__(256) __nv_bfloat16 g_wff2[(size_t)L_*256*1024];
__device__ __align__(256) __nv_bfloat16 g_wfm1[512*KP_];
__device__ __align__(256) __nv_bfloat16 g_wfm2[512*512];

// ============================ streaming bf16 HMMA GEMM (R10/R14) ============================
// C[M,N] = A[M,K] @ W[N,K]^T + bias.  EPI: 0 none, 1 silu, 2 +res(bf16)
// 128x128 tile, BK=64, 3 smem stages (96KB) -> 2 CTAs/SM, prefetch dist 2.
#define GSMEM (3*32768 + 1024)

static __device__ __forceinline__ void load_stage(
    uint32_t ab, int s, const __nv_bfloat16* A, const __nv_bfloat16* W,
    int K, int bm, int bn, int k0, int tid)
{
    uint32_t as_ = ab + s*32768;
    uint32_t bs_ = as_ + 16384;
    const __nv_bfloat16* Ap = A + (size_t)bm*K + k0;
    const __nv_bfloat16* Wp = W + (size_t)bn*K + k0;
#pragma unroll
    for (int t = 0; t < 4; t++) {
        int idx = tid + t*256;
        int row = idx >> 3, c16 = idx & 7;
        uint32_t off = (uint32_t)(row*128 + c16*16);
        cpa16(as_ + SWZ(off), Ap + (size_t)row*K + c16*8);
    }
#pragma unroll
    for (int t = 0; t < 4; t++) {
        int idx = tid + t*256;
        int row = idx >> 3, c16 = idx & 7;
        uint32_t off = (uint32_t)(row*128 + c16*16);
        cpa16(bs_ + SWZ(off), Wp + (size_t)row*K + c16*8);
    }
}

template<int EPI, int OUTBF>
__global__ __launch_bounds__(256, 2)
void gemm_tc(const __nv_bfloat16* __restrict__ A, const __nv_bfloat16* __restrict__ W,
             const float* __restrict__ bias, void* __restrict__ Cout,
             const void* __restrict__ res, int M, int N, int K)
{
    extern __shared__ char smem[];
    const int tid = threadIdx.x;
    uint32_t sraw = s2u(smem);
    uint32_t ab = (sraw + 1023) & ~1023u;
    char* smemc = smem + (ab - sraw);
    const int bm = blockIdx.y * 128;
    const int bn = blockIdx.x * 128;
    const int lane = tid & 31, wid = tid >> 5;
    const int wm = (wid & 3) * 32;
    const int wn = (wid >> 2) * 64;

    float acc[2][8][4];
#pragma unroll
    for (int a = 0; a < 2; a++)
#pragma unroll
        for (int b = 0; b < 8; b++)
#pragma unroll
            for (int c = 0; c < 4; c++) acc[a][b][c] = 0.f;

    const int nch = K >> 6;
    load_stage(ab, 0, A, W, K, bm, bn, 0,  tid); CP_COMMIT();
    load_stage(ab, 1, A, W, K, bm, bn, 64, tid); CP_COMMIT();

    const int r16 = lane & 15;
    const uint32_t cg = (uint32_t)((lane >> 4) << 4);

    int s = 0;
    for (int i = 0; i < nch; i++) {
        CP_WAIT1();
        __syncthreads();
        if (i + 2 < nch) {
            int s2 = s + 2; if (s2 >= 3) s2 -= 3;
            load_stage(ab, s2, A, W, K, bm, bn, (i+2)*64, tid);
        }
        CP_COMMIT();

        const uint32_t as_ = ab + s*32768;
        const uint32_t bs_ = as_ + 16384;
#pragma unroll
        for (int k16 = 0; k16 < 4; k16++) {
            uint32_t af[2][4], bfr[4][4];
#pragma unroll
            for (int mt = 0; mt < 2; mt++) {
                uint32_t off = (uint32_t)((wm + mt*16 + r16)*128 + k16*32) + cg;
                ldm4(as_ + SWZ(off), af[mt]);
            }
#pragma unroll
            for (int nt2 = 0; nt2 < 4; nt2++) {
                uint32_t off = (uint32_t)((wn + nt2*16 + r16)*128 + k16*32) + cg;
                ldm4(bs_ + SWZ(off), bfr[nt2]);
            }
#pragma unroll
            for (int mt = 0; mt < 2; mt++)
#pragma unroll
                for (int nt2 = 0; nt2 < 4; nt2++) {
                    mma16816(acc[mt][nt2*2],   af[mt][0], af[mt][1], af[mt][2], af[mt][3],
                             bfr[nt2][0], bfr[nt2][2]);
                    mma16816(acc[mt][nt2*2+1], af[mt][0], af[mt][1], af[mt][2], af[mt][3],
                             bfr[nt2][1], bfr[nt2][3]);
                }
        }
        if (++s >= 3) s = 0;
    }
    CP_WAIT0();
    __syncthreads();

    // epilogue: regs -> smem (stride 132) -> coalesced fused stores
    float* smemT = (float*)smemc;
    {
        const int r4 = lane >> 2;
        const int c2 = (lane & 3) << 1;
#pragma unroll
        for (int mt = 0; mt < 2; mt++)
#pragma unroll
            for (int nt = 0; nt < 8; nt++) {
                int row = wm + mt*16 + r4;
                int col = wn + nt*8 + c2;
                *(float2*)&smemT[row*132 + col]     = make_float2(acc[mt][nt][0], acc[mt][nt][1]);
                *(float2*)&smemT[(row+8)*132 + col] = make_float2(acc[mt][nt][2], acc[mt][nt][3]);
            }
    }
    __syncthreads();
#pragma unroll
    for (int it = 0; it < 16; it++) {
        int idx = tid + it*256;
        int row = idx >> 5;
        int c4  = (idx & 31) << 2;
        float4 v = *(float4*)&smemT[row*132 + c4];
        float4 bb = *(const float4*)&bias[bn + c4];
        v.x += bb.x; v.y += bb.y; v.z += bb.z; v.w += bb.w;
        if (EPI == 1) {
            v.x *= 1.f/(1.f + __expf(-v.x));
            v.y *= 1.f/(1.f + __expf(-v.y));
            v.z *= 1.f/(1.f + __expf(-v.z));
            v.w *= 1.f/(1.f + __expf(-v.w));
        }
        size_t g = (size_t)(bm + row)*N + bn + c4;
        if (EPI == 2) {
            uint2 rr = *(const uint2*)((const __nv_bfloat16*)res + g);
            __nv_bfloat162 r0 = *(__nv_bfloat162*)&rr.x;
            __nv_bfloat162 r1 = *(__nv_bfloat162*)&rr.y;
            v.x += __bfloat162float(r0.x); v.y += __bfloat162float(r0.y);
            v.z += __bfloat162float(r1.x); v.w += __bfloat162float(r1.y);
        }
        if (OUTBF) {
            __nv_bfloat162 p0 = __floats2bfloat162_rn(v.x, v.y);
            __nv_bfloat162 p1 = __floats2bfloat162_rn(v.z, v.w);
            uint2 u2;
            u2.x = *(uint32_t*)&p0; u2.y = *(uint32_t*)&p1;
            *(uint2*)((__nv_bfloat16*)Cout + g) = u2;
        } else {
            *(float4*)((float*)Cout + g) = v;
        }
    }
}

// ============================ aux kernels ============================
// vectorized fp32 -> bf16 (n multiple of 4)
__global__ void k_cvt(const float* __restrict__ s, __nv_bfloat16* __restrict__ d, int n)
{
    for (int i = (blockIdx.x*blockDim.x + threadIdx.x)*4; i < n; i += gridDim.x*blockDim.x*4) {
        float4 v = *(const float4*)(s + i);
        __nv_bfloat162 p0 = __floats2bfloat162_rn(v.x, v.y);
        __nv_bfloat162 p1 = __floats2bfloat162_rn(v.z, v.w);
        uint2 u2;
        u2.x = *(uint32_t*)&p0; u2.y = *(uint32_t*)&p1;
        *(uint2*)(d + i) = u2;
    }
}

__global__ void k_cat(const float* __restrict__ b1, const float* __restrict__ b2,
                      float* __restrict__ d)
{
    int i = blockIdx.x*blockDim.x + threadIdx.x;   // 6144 total
    d[i] = (i < 3072) ? b1[i] : b2[i - 3072];
}

__global__ __launch_bounds__(256)
void k_stroke(const float* __restrict__ strokes, const float* __restrict__ sp_w,
              const float* __restrict__ sp_b, const float* __restrict__ pos,
              __nv_bfloat16* __restrict__ x)
{
    int row = blockIdx.x;
    int t = row % T_;
    int d = threadIdx.x;
    float acc = sp_b[d] + pos[t*D_ + d];
#pragma unroll
    for (int j = 0; j < 8; j++)
        acc += strokes[(size_t)row*8 + j] * sp_w[d*8 + j];
    x[(size_t)row*D_ + d] = __float2bfloat16(acc);
}

static __device__ __forceinline__ void unp8(uint4 u, float* v){
    __nv_bfloat162 p0 = *(__nv_bfloat162*)&u.x;
    __nv_bfloat162 p1 = *(__nv_bfloat162*)&u.y;
    __nv_bfloat162 p2 = *(__nv_bfloat162*)&u.z;
    __nv_bfloat162 p3 = *(__nv_bfloat162*)&u.w;
    v[0] = __bfloat162float(p0.x); v[1] = __bfloat162float(p0.y);
    v[2] = __bfloat162float(p1.x); v[3] = __bfloat162float(p1.y);
    v[4] = __bfloat162float(p2.x); v[5] = __bfloat162float(p2.y);
    v[6] = __bfloat162float(p3.x); v[7] = __bfloat162float(p3.y);
}

// warp-per-row adaLN modulate
__global__ __launch_bounds__(256)
void k_modln(const __nv_bfloat16* __restrict__ x, const float* __restrict__ ss,
             __nv_bfloat16* __restrict__ x2, int off)
{
    int w = threadIdx.x >> 5, ln = threadIdx.x & 31;
    int row = blockIdx.x*8 + w;
    int b = row / T_;
    float v[8];
    unp8(*(const uint4*)(x + (size_t)row*D_ + ln*8), v);
    float s = 0.f, q = 0.f;
#pragma unroll
    for (int j = 0; j < 8; j++) { s += v[j]; q += v[j]*v[j]; }
#pragma unroll
    for (int o = 16; o; o >>= 1) {
        s += __shfl_xor_sync(0xffffffffu, s, o);
        q += __shfl_xor_sync(0xffffffffu, q, o);
    }
    float mean = s * (1.f/256.f);
    float rstd = rsqrtf(q * (1.f/256.f) - mean*mean + 1e-5f);
    const float* ssb = ss + (size_t)b*NAD_ + off;
    float sc[8], sh[8];
    *(float4*)&sc[0] = *(const float4*)&ssb[ln*8];
    *(float4*)&sc[4] = *(const float4*)&ssb[ln*8 + 4];
    *(float4*)&sh[0] = *(const float4*)&ssb[256 + ln*8];
    *(float4*)&sh[4] = *(const float4*)&ssb[256 + ln*8 + 4];
    float o8[8];
#pragma unroll
    for (int j = 0; j < 8; j++)
        o8[j] = (1.f + sc[j])*((v[j] - mean)*rstd) + sh[j];
    __nv_bfloat162 p0 = __floats2bfloat162_rn(o8[0], o8[1]);
    __nv_bfloat162 p1 = __floats2bfloat162_rn(o8[2], o8[3]);
    __nv_bfloat162 p2 = __floats2bfloat162_rn(o8[4], o8[5]);
    __nv_bfloat162 p3 = __floats2bfloat162_rn(o8[6], o8[7]);
    uint4 u4;
    u4.x = *(uint32_t*)&p0; u4.y = *(uint32_t*)&p1;
    u4.z = *(uint32_t*)&p2; u4.w = *(uint32_t*)&p3;
    *(uint4*)&x2[(size_t)row*D_ + ln*8] = u4;
}

// ============================ attention (R14 compute; vectorized staging) ============================
// One CTA per batch element. K/V fp32 [T][256] (compute reads are warp broadcasts).
// Q staged per-head padded [h][t][33]. Staging reads bf16 PAIRS (u32, full sectors)
// in three power-of-two passes; float2 smem stores (conflict-free).
#define QSTR 33
#define ASMEM (2*T_*256*4 + H_*T_*QSTR*4)   // 93120
__global__ __launch_bounds__(256)
void k_attn(const __nv_bfloat16* __restrict__ qkv, __nv_bfloat16* __restrict__ o)
{
    extern __shared__ float att[];
    float* ks = att;                 // [T_][256]
    float* vs = att + T_*256;        // [T_][256]
    float* qs = att + 2*T_*256;      // [H_][T_][QSTR]
    int b = blockIdx.x;
    int tid = threadIdx.x;
    int h = tid >> 5, ln = tid & 31;

    const uint32_t* q32 = (const uint32_t*)qkv;   // row stride 384 u32
    // Q pass: 30*128 pairs
#pragma unroll
    for (int it = 0; it < 15; it++) {
        int i = tid + it*256;
        int t = i >> 7, d2 = i & 127;
        uint32_t pr = q32[((size_t)(b*T_ + t))*384 + d2];
        __nv_bfloat162 p = *(__nv_bfloat162*)&pr;
        int d = d2*2;
        int hh = d >> 5, dd = d & 31;
        float* qd = qs + hh*(T_*QSTR) + t*QSTR + dd;
        qd[0] = __bfloat162float(p.x);
        qd[1] = __bfloat162float(p.y);
    }
    // K pass
#pragma unroll
    for (int it = 0; it < 15; it++) {
        int i = tid + it*256;
        int t = i >> 7, d2 = i & 127;
        uint32_t pr = q32[((size_t)(b*T_ + t))*384 + 128 + d2];
        __nv_bfloat162 p = *(__nv_bfloat162*)&pr;
        *(float2*)&ks[t*256 + d2*2] = make_float2(__bfloat162float(p.x), __bfloat162float(p.y));
    }
    // V pass
#pragma unroll
    for (int it = 0; it < 15; it++) {
        int i = tid + it*256;
        int t = i >> 7, d2 = i & 127;
        uint32_t pr = q32[((size_t)(b*T_ + t))*384 + 256 + d2];
        __nv_bfloat162 p = *(__nv_bfloat162*)&pr;
        *(float2*)&vs[t*256 + d2*2] = make_float2(__bfloat162float(p.x), __bfloat162float(p.y));
    }
    __syncthreads();

    if (ln < T_) {
        const int q = ln;
        float qreg[32];
        const float* qh = qs + h*(T_*QSTR) + q*QSTR;
#pragma unroll
        for (int d = 0; d < 32; d++) qreg[d] = qh[d];
        const float* kh = ks + h*32;
        const float* vh = vs + h*32;
        const float scale = 0.17677669529663687f;

        float sc[T_];
#pragma unroll
        for (int k = 0; k < T_; k++) {
            float acc = 0.f;
#pragma unroll
            for (int d = 0; d < 32; d++) acc += qreg[d]*kh[k*256 + d];
            sc[k] = (k <= q) ? acc*scale : -1e30f;
        }
        float mx = -1e30f;
#pragma unroll
        for (int k = 0; k < T_; k++) mx = fmaxf(mx, sc[k]);
        float sm = 0.f;
#pragma unroll
        for (int k = 0; k < T_; k++) { sc[k] = __expf(sc[k] - mx); sm += sc[k]; }
        float inv = 1.f/sm;

        float o32[32];
#pragma unroll
        for (int d = 0; d < 32; d++) o32[d] = 0.f;
#pragma unroll
        for (int k = 0; k < T_; k++) {
            float a = sc[k]*inv;
            if (k <= q) {
#pragma unroll
                for (int d = 0; d < 32; d++) o32[d] += a*vh[k*256 + d];
            }
        }
        __nv_bfloat16* op = o + ((size_t)(b*T_ + q))*256 + h*32;
#pragma unroll
        for (int d4 = 0; d4 < 4; d4++) {
            __nv_bfloat162 p0 = __floats2bfloat162_rn(o32[d4*8+0], o32[d4*8+1]);
            __nv_bfloat162 p1 = __floats2bfloat162_rn(o32[d4*8+2], o32[d4*8+3]);
            __nv_bfloat162 p2 = __floats2bfloat162_rn(o32[d4*8+4], o32[d4*8+5]);
            __nv_bfloat162 p3 = __floats2bfloat162_rn(o32[d4*8+6], o32[d4*8+7]);
            uint4 u4;
            u4.x = *(uint32_t*)&p0; u4.y = *(uint32_t*)&p1;
            u4.z = *(uint32_t*)&p2; u4.w = *(uint32_t*)&p3;
            *(uint4*)(op + d4*8) = u4;
        }
    }
}

// fused head: final LN on last token + xin tail + u
__global__ __launch_bounds__(256)
void k_head(const __nv_bfloat16* __restrict__ x, const float* __restrict__ g,
            const float* __restrict__ be, const float* __restrict__ a_tar,
            const float* __restrict__ a_src, const float* __restrict__ t,
            __nv_bfloat16* __restrict__ xin, float* __restrict__ u)
{
    int w = threadIdx.x >> 5, ln = threadIdx.x & 31;
    int b = blockIdx.x*8 + w;
    float v[8];
    unp8(*(const uint4*)(x + ((size_t)(b*T_ + T_ - 1))*D_ + ln*8), v);
    float s = 0.f, q = 0.f;
#pragma unroll
    for (int j = 0; j < 8; j++) { s += v[j]; q += v[j]*v[j]; }
#pragma unroll
    for (int o = 16; o; o >>= 1) {
        s += __shfl_xor_sync(0xffffffffu, s, o);
        q += __shfl_xor_sync(0xffffffffu, q, o);
    }
    float mean = s * (1.f/256.f);
    float rstd = rsqrtf(q * (1.f/256.f) - mean*mean + 1e-5f);
    size_t base = (size_t)b*KP_;
#pragma unroll
    for (int j = 0; j < 8; j++) {
        int d = ln*8 + j;
        xin[base + d] = __float2bfloat16(((v[j] - mean)*rstd)*g[d] + be[d]);
    }
    float tb = t[b];
    if (ln < 8) {
        float as = a_src[b*8+ln], at = a_tar[b*8+ln];
        xin[base + 256 + ln] = __float2bfloat16((1.f - tb)*as + tb*at);
        u[b*8+ln] = at - as;
    } else if (ln < 24) {
        int j = ln - 8;
        float freq = __expf(-9.210340371976184f * (float)j / 15.f);
        float arg = tb * freq;
        xin[base + 264 + j] = __float2bfloat16(sinf(arg));
        xin[base + 280 + j] = __float2bfloat16(cosf(arg));
    } else {
        int j0 = (ln - 24) * 3;
#pragma unroll
        for (int k = 0; k < 3; k++)
            xin[base + 296 + j0 + k] = __float2bfloat16(0.f);
    }
}

__global__ void k_padw(const float* __restrict__ w, __nv_bfloat16* __restrict__ wp)
{
    int n = blockIdx.x, k = threadIdx.x;
    wp[n*KP_ + k] = __float2bfloat16(k < 296 ? w[n*296 + k] : 0.f);
}

__global__ __launch_bounds__(256)
void k_fm3(const __nv_bfloat16* __restrict__ f2, const float* __restrict__ w3,
           const float* __restrict__ b3, const float* __restrict__ u,
           float* __restrict__ part)
{
    __shared__ float sp[8];
    int w = threadIdx.x >> 5, ln = threadIdx.x & 31;
    int b = blockIdx.x * 8 + w;
    float lsum = 0.f;
    const __nv_bfloat16* fr = f2 + (size_t)b*512;
#pragma unroll
    for (int n = 0; n < 8; n++) {
        const float* wr = w3 + n*512;
        float p = 0.f;
        for (int k = ln; k < 512; k += 32) p += __bfloat162float(fr[k])*wr[k];
#pragma unroll
        for (int o = 16; o; o >>= 1) p += __shfl_xor_sync(0xffffffffu, p, o);
        if (ln == 0) {
            float d = p + b3[n] - u[b*8+n];
            lsum += d*d;
        }
    }
    if (ln == 0) sp[w] = lsum;
    __syncthreads();
    if (threadIdx.x == 0) {
        float s = 0.f;
        for (int i = 0; i < 8; i++) s += sp[i];
        part[blockIdx.x] = s;
    }
}

__global__ void k_reduce(const float* __restrict__ part, float* __restrict__ out)
{
    __shared__ float sp[1024];
    int i = threadIdx.x;
    sp[i] = part[i];
    __syncthreads();
    for (int s = 512; s; s >>= 1) { if (i < s) sp[i] += sp[i+s]; __syncthreads(); }
    if (i == 0) out[0] = sp[0] * (1.f / (float)(B_*SD_));
}

// ============================ launch ============================
extern "C" void kernel_launch(void* const* d_in, const int* in_sizes, int n_in,
                              void* d_out, int out_size)
{
    const float* strokes  = (const float*)d_in[0];
    const float* canvas   = (const float*)d_in[1];
    const float* a_tar    = (const float*)d_in[2];
    const float* a_src    = (const float*)d_in[3];
    const float* t_in     = (const float*)d_in[4];
    const float* ce_w1    = (const float*)d_in[5];
    const float* ce_b1    = (const float*)d_in[6];
    const float* ce_w2    = (const float*)d_in[7];
    const float* ce_b2    = (const float*)d_in[8];
    const float* sp_w     = (const float*)d_in[9];
    const float* sp_b     = (const float*)d_in[10];
    const float* pos_emb  = (const float*)d_in[11];
    const float* adaln1_w = (const float*)d_in[12];
    const float* adaln1_b = (const float*)d_in[13];
    const float* inproj_w = (const float*)d_in[14];
    const float* inproj_b = (const float*)d_in[15];
    const float* outproj_w= (const float*)d_in[16];
    const float* outproj_b= (const float*)d_in[17];
    const float* adaln2_w = (const float*)d_in[18];
    const float* adaln2_b = (const float*)d_in[19];
    const float* ff1_w    = (const float*)d_in[20];
    const float* ff1_b    = (const float*)d_in[21];
    const float* ff2_w    = (const float*)d_in[22];
    const float* ff2_b    = (const float*)d_in[23];
    const float* on_g     = (const float*)d_in[24];
    const float* on_b     = (const float*)d_in[25];
    const float* fm_w1    = (const float*)d_in[26];
    const float* fm_b1    = (const float*)d_in[27];
    const float* fm_w2    = (const float*)d_in[28];
    const float* fm_b2    = (const float*)d_in[29];
    const float* fm_w3    = (const float*)d_in[30];
    const float* fm_b3    = (const float*)d_in[31];
    float* out = (float*)d_out;

    float *ss, *adb, *u, *part;
    __nv_bfloat16 *xb, *x2b, *hb, *cb, *canvb, *f1b, *f2b, *xinb;
    __nv_bfloat16 *wce1, *wce2, *wad, *winp, *wout, *wff1, *wff2, *wfm1, *wfm2;
    cudaGetSymbolAddress((void**)&ss,   g_ss);
    cudaGetSymbolAddress((void**)&adb,  g_adb);
    cudaGetSymbolAddress((void**)&u,    g_u);
    cudaGetSymbolAddress((void**)&part, g_part);
    cudaGetSymbolAddress((void**)&xb,   g_xb);
    cudaGetSymbolAddress((void**)&x2b,  g_x2b);
    cudaGetSymbolAddress((void**)&hb,   g_hb);
    cudaGetSymbolAddress((void**)&cb,   g_cb);
    cudaGetSymbolAddress((void**)&canvb,g_canvb);
    cudaGetSymbolAddress((void**)&f1b,  g_f1b);
    cudaGetSymbolAddress((void**)&f2b,  g_f2b);
    cudaGetSymbolAddress((void**)&xinb, g_xinb);
    cudaGetSymbolAddress((void**)&wce1, g_wce1);
    cudaGetSymbolAddress((void**)&wce2, g_wce2);
    cudaGetSymbolAddress((void**)&wad,  g_wad);
    cudaGetSymbolAddress((void**)&winp, g_winp);
    cudaGetSymbolAddress((void**)&wout, g_wout);
    cudaGetSymbolAddress((void**)&wff1, g_wff1);
    cudaGetSymbolAddress((void**)&wff2, g_wff2);
    cudaGetSymbolAddress((void**)&wfm1, g_wfm1);
    cudaGetSymbolAddress((void**)&wfm2, g_wfm2);

    cudaFuncSetAttribute(gemm_tc<0,0>, cudaFuncAttributeMaxDynamicSharedMemorySize, GSMEM);
    cudaFuncSetAttribute(gemm_tc<0,1>, cudaFuncAttributeMaxDynamicSharedMemorySize, GSMEM);
    cudaFuncSetAttribute(gemm_tc<1,1>, cudaFuncAttributeMaxDynamicSharedMemorySize, GSMEM);
    cudaFuncSetAttribute(gemm_tc<2,1>, cudaFuncAttributeMaxDynamicSharedMemorySize, GSMEM);
    cudaFuncSetAttribute(k_attn,       cudaFuncAttributeMaxDynamicSharedMemorySize, ASMEM);

    // weight + input bf16 conversion
    k_cvt<<<1024, 256>>>(canvas,   canvb, B_*384);
    k_cvt<<<256,  256>>>(ce_w1,    wce1,  512*384);
    k_cvt<<<256,  256>>>(ce_w2,    wce2,  256*512);
    k_cvt<<<512,  256>>>(adaln1_w, wad,             L_*512*256);
    k_cvt<<<512,  256>>>(adaln2_w, wad + 3072*256,  L_*512*256);
    k_cat<<<24, 256>>>(adaln1_b, adaln2_b, adb);
    k_cvt<<<512,  256>>>(inproj_w, winp,  L_*768*256);
    k_cvt<<<512,  256>>>(outproj_w,wout,  L_*256*256);
    k_cvt<<<1024, 256>>>(ff1_w,    wff1,  L_*1024*256);
    k_cvt<<<1024, 256>>>(ff2_w,    wff2,  L_*256*1024);
    k_cvt<<<256,  256>>>(fm_w2,    wfm2,  512*512);
    k_padw<<<512, KP_>>>(fm_w1, wfm1);

    // canvas encoder
    gemm_tc<1,1><<<dim3(4,  64), 256, GSMEM>>>(canvb, wce1, ce_b1, f1b, nullptr, B_, 512, 384);
    gemm_tc<0,1><<<dim3(2,  64), 256, GSMEM>>>(f1b,   wce2, ce_b2, cb,  nullptr, B_, 256, 512);

    // all 12 adaLN projections in one batched GEMM: ss[B, 6144]
    gemm_tc<0,0><<<dim3(48, 64), 256, GSMEM>>>(cb, wad, adb, ss, nullptr, B_, NAD_, 256);

    // stroke projection
    k_stroke<<<BT_, 256>>>(strokes, sp_w, sp_b, pos_emb, xb);

    for (int l = 0; l < L_; l++) {
        k_modln<<<BT_/8, 256>>>(xb, ss, x2b, l*512);
        gemm_tc<0,1><<<dim3(6, 1920), 256, GSMEM>>>(x2b, winp + (size_t)l*768*256,
                                                    inproj_b + l*768, hb, nullptr, BT_, 768, 256);
        k_attn<<<B_, 256, ASMEM>>>(hb, x2b);
        gemm_tc<2,1><<<dim3(2, 1920), 256, GSMEM>>>(x2b, wout + (size_t)l*256*256,
                                                    outproj_b + l*256, xb, xb, BT_, 256, 256);
        k_modln<<<BT_/8, 256>>>(xb, ss, x2b, 3072 + l*512);
        gemm_tc<1,1><<<dim3(8, 1920), 256, GSMEM>>>(x2b, wff1 + (size_t)l*1024*256,
                                                    ff1_b + l*1024, hb, nullptr, BT_, 1024, 256);
        gemm_tc<2,1><<<dim3(2, 1920), 256, GSMEM>>>(hb, wff2 + (size_t)l*256*1024,
                                                    ff2_b + l*256, xb, xb, BT_, 256, 1024);
    }

    // output head
    k_head<<<B_/8, 256>>>(xb, on_g, on_b, a_tar, a_src, t_in, xinb, u);
    gemm_tc<1,1><<<dim3(4, 64), 256, GSMEM>>>(xinb, wfm1, fm_b1, f1b, nullptr, B_, 512, KP_);
    gemm_tc<1,1><<<dim3(4, 64), 256, GSMEM>>>(f1b,  wfm2, fm_b2, f2b, nullptr, B_, 512, 512);
    k_fm3<<<B_/8, 256>>>(f2b, fm_w3, fm_b3, u, part);
    k_reduce<<<1, 1024>>>(part, out);
}